// round 2
// baseline (speedup 1.0000x reference)
#include <cuda_runtime.h>
#include <stdint.h>

// RGBMem: NCE memory-bank kernel.
//   logits[b,k] = dot(memory[row(b,k)], x[b]) / T,  row(b,0)=y[b], else idx[b,k]
//   labels = zeros
//   new_memory = memory with rows y[b] := normalize(0.5*memory[y]+0.5*x[b])
// Output (float32 buffer): [logits (bsz*Kp1)] [labels gap] [memory (n_data*128)]

#define T_INV (1.0f / 0.07f)

// Flag: 1 if y/idx are int64 on device, 0 if int32. Set by sniff_kernel.
__device__ int g_idx64;

__device__ __forceinline__ long long load_index(const void* p, long long i,
                                                int is64) {
    if (is64) return ((const long long*)p)[i];
    return (long long)((const int*)p)[i];
}

// ---------------------------------------------------------------------------
// Sniff index dtype from idx: values < 5e5 << 2^31, so if data is int64 the
// odd 32-bit words (high halves) of the first 16 entries are all zero.
// If data is int32, those words are random indices (P[all zero] ~ 0).
// ---------------------------------------------------------------------------
__global__ void sniff_kernel(const unsigned int* __restrict__ idx_words) {
    int is64 = 1;
    for (int i = 0; i < 16; i++) {
        if (idx_words[2 * i + 1] != 0u) { is64 = 0; break; }
    }
    g_idx64 = is64;
}

// ---------------------------------------------------------------------------
// Bulk copy of memory table -> output region (float4, grid-stride)
// ---------------------------------------------------------------------------
__global__ void copy_mem_kernel(const float4* __restrict__ src,
                                float4* __restrict__ dst, long long n4) {
    long long i = (long long)blockIdx.x * blockDim.x + threadIdx.x;
    long long stride = (long long)gridDim.x * blockDim.x;
    for (; i < n4; i += stride) dst[i] = src[i];
}

// ---------------------------------------------------------------------------
// Logits: one warp per (b,k). Lane loads one float4 of the 512B memory row.
// x staged in shared (8KB, loaded once per block).
// ---------------------------------------------------------------------------
__global__ void logits_kernel(const float* __restrict__ x,
                              const void* __restrict__ y,
                              const void* __restrict__ idx,
                              const float* __restrict__ memory,
                              float* __restrict__ logits,
                              int bsz, int Kp1, long long n_data) {
    __shared__ float4 xs[16 * 32];
    int tid = threadIdx.x;
    int is64 = g_idx64;
    int nx4 = bsz * 32;
    for (int i = tid; i < nx4; i += blockDim.x) xs[i] = ((const float4*)x)[i];
    __syncthreads();

    int lane = tid & 31;
    long long warp = ((long long)blockIdx.x * blockDim.x + tid) >> 5;
    long long nwarps = ((long long)gridDim.x * blockDim.x) >> 5;
    long long total = (long long)bsz * Kp1;

    for (long long i = warp; i < total; i += nwarps) {
        int b = (int)(i / Kp1);
        int k = (int)(i - (long long)b * Kp1);
        long long row = (k == 0) ? load_index(y, b, is64)
                                 : load_index(idx, i, is64);
        // defensive clamp: wrong dtype theory -> rel_err signal, not a crash
        row = row < 0 ? 0 : (row >= n_data ? n_data - 1 : row);
        const float4* mr = (const float4*)(memory + row * 128);
        float4 m = mr[lane];
        float4 xv = xs[b * 32 + lane];
        float s = m.x * xv.x + m.y * xv.y + m.z * xv.z + m.w * xv.w;
        #pragma unroll
        for (int off = 16; off; off >>= 1)
            s += __shfl_xor_sync(0xffffffffu, s, off);
        if (lane == 0) logits[i] = s * T_INV;
    }
}

// ---------------------------------------------------------------------------
// EMA update + normalize of the bsz touched rows; zero the labels gap.
// One block per batch element, 128 threads (one per dim).
// ---------------------------------------------------------------------------
__global__ void update_kernel(const float* __restrict__ x,
                              const void* __restrict__ y,
                              const float* __restrict__ memory,
                              float* __restrict__ out_mem,
                              float* __restrict__ out_labels,
                              int label_elems, long long n_data) {
    int b = blockIdx.x;
    int t = threadIdx.x;
    int is64 = g_idx64;
    long long row = load_index(y, b, is64);
    row = row < 0 ? 0 : (row >= n_data ? n_data - 1 : row);

    float v = memory[row * 128 + t] * 0.5f + x[b * 128 + t] * 0.5f;

    float s = v * v;
    #pragma unroll
    for (int off = 16; off; off >>= 1)
        s += __shfl_xor_sync(0xffffffffu, s, off);
    __shared__ float ws[4];
    if ((t & 31) == 0) ws[t >> 5] = s;
    __syncthreads();
    float tot = ws[0] + ws[1] + ws[2] + ws[3];
    float denom = fmaxf(sqrtf(tot), 1e-12f);

    out_mem[row * 128 + t] = v / denom;

    if (b == 0 && t < label_elems) out_labels[t] = 0.0f;
}

// ---------------------------------------------------------------------------
extern "C" void kernel_launch(void* const* d_in, const int* in_sizes, int n_in,
                              void* d_out, int out_size) {
    const float* x      = (const float*)d_in[0];   // [bsz, 128]
    const void*  y      = d_in[1];                 // [bsz]       int32 or int64
    const void*  idx    = d_in[2];                 // [bsz, K+1]  int32 or int64
    const float* memory = (const float*)d_in[3];   // [n_data, 128]

    int bsz = in_sizes[1];
    int Kp1 = in_sizes[2] / bsz;
    long long mem_elems = (long long)in_sizes[3];
    long long n_data = mem_elems / 128;
    long long logits_elems = (long long)bsz * Kp1;

    float* out = (float*)d_out;
    float* out_logits = out;
    long long mem_off = (long long)out_size - mem_elems;
    if (mem_off < logits_elems) mem_off = logits_elems;  // safety
    float* out_mem = out + mem_off;
    float* out_labels = out + logits_elems;
    int label_elems = (int)(mem_off - logits_elems);

    // 0) dtype sniff (device-side, deterministic)
    sniff_kernel<<<1, 1>>>((const unsigned int*)idx);
    // 1) bulk memory copy (precedes row-scatter update; stream ordered)
    copy_mem_kernel<<<2048, 256>>>((const float4*)memory, (float4*)out_mem,
                                   mem_elems / 4);
    // 2) gathered dot-product logits
    logits_kernel<<<1184, 256>>>(x, y, idx, memory, out_logits,
                                 bsz, Kp1, n_data);
    // 3) EMA + normalize scatter, zero labels
    update_kernel<<<bsz, 128>>>(x, y, memory, out_mem, out_labels,
                                label_elems, n_data);
}